// round 1
// baseline (speedup 1.0000x reference)
#include <cuda_runtime.h>

#define RES      64
#define R3       (RES * RES * RES)      // 262144
#define NWORDS   (R3 / 32)              // 8192  (32 KB bitmask)
#define NB       592                    // 148 SMs * 4
#define NT       256

// ---- scratch (no allocations allowed) --------------------------------------
__device__ float4   g_table[R3];        // closest point per voxel (w unused)
__device__ unsigned g_bits[NWORDS];     // voxel occupancy bitmask
__device__ float    g_params[64];       // [t*8+{0..4}]: nx,ny,nz,s,s*d ; [24+t*12+{0..8}]: rot matrix
__device__ float    g_partials[NB];

// ---- prep: transform parameters --------------------------------------------
__global__ void prep_params_k(const float* __restrict__ planes,
                              const float* __restrict__ axes) {
    if (threadIdx.x == 0) {
#pragma unroll
        for (int t = 0; t < 3; t++) {
            float nx = planes[4*t+0], ny = planes[4*t+1],
                  nz = planes[4*t+2], d  = planes[4*t+3];
            float s = 2.0f / (nx*nx + ny*ny + nz*nz);
            g_params[t*8+0] = nx;
            g_params[t*8+1] = ny;
            g_params[t*8+2] = nz;
            g_params[t*8+3] = s;
            g_params[t*8+4] = s * d;
        }
#pragma unroll
        for (int t = 0; t < 3; t++) {
            float w = axes[4*t+0], x = axes[4*t+1],
                  y = axes[4*t+2], z = axes[4*t+3];
            // q p q* (pure p, q unnormalized) = [(w^2-|v|^2)I + 2 v v^T + 2 w [v]x] p
            float* m = &g_params[24 + t*12];
            m[0] = w*w + x*x - y*y - z*z;
            m[1] = 2.0f * (x*y - w*z);
            m[2] = 2.0f * (x*z + w*y);
            m[3] = 2.0f * (x*y + w*z);
            m[4] = w*w - x*x + y*y - z*z;
            m[5] = 2.0f * (y*z - w*x);
            m[6] = 2.0f * (x*z - w*y);
            m[7] = 2.0f * (y*z + w*x);
            m[8] = w*w - x*x - y*y + z*z;
        }
    }
}

// ---- prep: float4 closest-point table + occupancy bitmask ------------------
__global__ void prep_table_k(const float* __restrict__ cp,
                             const int*   __restrict__ vox) {
    int i = blockIdx.x * blockDim.x + threadIdx.x;
    if (i < R3) {
        float4 v;
        v.x = cp[3*i + 0];
        v.y = cp[3*i + 1];
        v.z = cp[3*i + 2];
        v.w = 0.0f;
        g_table[i] = v;
    }
    if (i < NWORDS) {
        unsigned w = 0u;
#pragma unroll 8
        for (int j = 0; j < 32; j++)
            if (vox[i*32 + j] != 0) w |= (1u << j);
        g_bits[i] = w;
    }
}

// ---- one transformed-point tap: index, smem mask check, conditional gather --
__device__ __forceinline__ float tap(float x, float y, float z,
                                     const unsigned* __restrict__ s_bits) {
    int ix = min(max(__float2int_rd(x * 64.0f), 0), 63);
    int iy = min(max(__float2int_rd(y * 64.0f), 0), 63);
    int iz = min(max(__float2int_rd(z * 64.0f), 0), 63);
    int idx = (ix << 12) | (iy << 6) | iz;
    float r = 0.0f;
    if ((s_bits[idx >> 5] >> (idx & 31)) & 1u) {
        float4 c = __ldg(&g_table[idx]);
        float dx = x - c.x, dy = y - c.y, dz = z - c.z;
        r = sqrtf(fmaf(dx, dx, fmaf(dy, dy, dz * dz)));
    }
    return r;
}

// all 6 transforms for one point
__device__ __forceinline__ float point_all(float x, float y, float z,
                                           const float pn[3][5],
                                           const float m[3][9],
                                           const unsigned* __restrict__ s_bits) {
    float acc = 0.0f;
#pragma unroll
    for (int t = 0; t < 3; t++) {
        float dot  = fmaf(x, pn[t][0], fmaf(y, pn[t][1], z * pn[t][2]));
        float coef = fmaf(dot, pn[t][3], pn[t][4]);
        float tx = fmaf(-coef, pn[t][0], x);
        float ty = fmaf(-coef, pn[t][1], y);
        float tz = fmaf(-coef, pn[t][2], z);
        acc += tap(tx, ty, tz, s_bits);
    }
#pragma unroll
    for (int t = 0; t < 3; t++) {
        float tx = fmaf(x, m[t][0], fmaf(y, m[t][1], z * m[t][2]));
        float ty = fmaf(x, m[t][3], fmaf(y, m[t][4], z * m[t][5]));
        float tz = fmaf(x, m[t][6], fmaf(y, m[t][7], z * m[t][8]));
        acc += tap(tx, ty, tz, s_bits);
    }
    return acc;
}

// ---- main fused kernel ------------------------------------------------------
__global__ void __launch_bounds__(NT, 2)
symmetry_main_k(const float* __restrict__ sp, int npts) {
    __shared__ unsigned s_bits[NWORDS];   // 32 KB
    __shared__ float    s_red[NT / 32];

    for (int i = threadIdx.x; i < NWORDS; i += NT)
        s_bits[i] = g_bits[i];
    __syncthreads();

    // load precomputed params into registers (uniform across warp)
    float pn[3][5];
    float m[3][9];
#pragma unroll
    for (int t = 0; t < 3; t++) {
#pragma unroll
        for (int j = 0; j < 5; j++) pn[t][j] = g_params[t*8 + j];
#pragma unroll
        for (int j = 0; j < 9; j++) m[t][j]  = g_params[24 + t*12 + j];
    }

    const float4* sp4 = (const float4*)sp;
    int ngroups = npts >> 2;     // 4 points = 3 float4
    int stride  = gridDim.x * NT;
    float acc = 0.0f;

    for (int g = blockIdx.x * NT + threadIdx.x; g < ngroups; g += stride) {
        float4 A = __ldg(&sp4[3*g + 0]);
        float4 B = __ldg(&sp4[3*g + 1]);
        float4 C = __ldg(&sp4[3*g + 2]);
        float X[4] = {A.x, A.w, B.z, C.y};
        float Y[4] = {A.y, B.x, B.w, C.z};
        float Z[4] = {A.z, B.y, C.x, C.w};
#pragma unroll
        for (int k = 0; k < 4; k++)
            acc += point_all(X[k], Y[k], Z[k], pn, m, s_bits);
    }

    // tail (npts not divisible by 4) — handled by block 0 only
    int tail = npts & 3;
    if (tail && blockIdx.x == 0 && threadIdx.x < tail) {
        int i = npts - tail + threadIdx.x;
        acc += point_all(sp[3*i], sp[3*i+1], sp[3*i+2], pn, m, s_bits);
    }

    // deterministic block reduction
#pragma unroll
    for (int o = 16; o; o >>= 1)
        acc += __shfl_xor_sync(0xFFFFFFFFu, acc, o);
    int lane = threadIdx.x & 31;
    int wid  = threadIdx.x >> 5;
    if (lane == 0) s_red[wid] = acc;
    __syncthreads();
    if (threadIdx.x < NT / 32) {
        float v = s_red[threadIdx.x];
#pragma unroll
        for (int o = (NT / 64); o; o >>= 1)
            v += __shfl_xor_sync((1u << (NT/32)) - 1u, v, o);
        if (threadIdx.x == 0) g_partials[blockIdx.x] = v;
    }
}

// ---- final deterministic reduction ------------------------------------------
__global__ void final_reduce_k(float* __restrict__ out, float invN, int nb) {
    __shared__ float s_red[8];
    float v = 0.0f;
    for (int i = threadIdx.x; i < nb; i += 256)
        v += g_partials[i];
#pragma unroll
    for (int o = 16; o; o >>= 1)
        v += __shfl_xor_sync(0xFFFFFFFFu, v, o);
    int lane = threadIdx.x & 31;
    int wid  = threadIdx.x >> 5;
    if (lane == 0) s_red[wid] = v;
    __syncthreads();
    if (threadIdx.x < 8) {
        float u = s_red[threadIdx.x];
#pragma unroll
        for (int o = 4; o; o >>= 1)
            u += __shfl_xor_sync(0xFFu, u, o);
        if (threadIdx.x == 0) out[0] = u * invN;
    }
}

// ---- launch ------------------------------------------------------------------
extern "C" void kernel_launch(void* const* d_in, const int* in_sizes, int n_in,
                              void* d_out, int out_size) {
    const float* sp     = (const float*)d_in[0];   // sample_points (N,3)
    const float* cp     = (const float*)d_in[1];   // closest_points (R^3,3)
    const int*   vox    = (const int*)  d_in[2];   // voxels (R^3,)
    const float* planes = (const float*)d_in[3];   // (3,4)
    const float* axes   = (const float*)d_in[4];   // (3,4)
    int npts = in_sizes[0] / 3;

    prep_params_k<<<1, 32>>>(planes, axes);
    prep_table_k<<<(R3 + 255) / 256, 256>>>(cp, vox);
    symmetry_main_k<<<NB, NT>>>(sp, npts);
    final_reduce_k<<<1, 256>>>((float*)d_out, 1.0f / (float)npts, NB);
}

// round 2
// speedup vs baseline: 1.3547x; 1.3547x over previous
#include <cuda_runtime.h>

#define RES      64
#define R3       (RES * RES * RES)      // 262144
#define NWORDS   (R3 / 32)              // 8192  (32 KB bitmask)
#define NB       444                    // 148 SMs * 3 blocks
#define NT       256

// ---- scratch (no allocations allowed) --------------------------------------
__device__ float4   g_table[R3];        // closest point per voxel (w unused)
__device__ unsigned g_bits[NWORDS];     // voxel occupancy bitmask
__device__ float    g_params[64];       // [t*8+{0..4}]: refl ; [24+t*12+{0..8}]: rot matrix
__device__ float    g_partials[NB];
__device__ int      g_counter;

// ---- prep: params + float4 table + bitmask + counter reset (one kernel) -----
__global__ void prep_k(const float* __restrict__ cp,
                       const int*   __restrict__ vox,
                       const float* __restrict__ planes,
                       const float* __restrict__ axes) {
    int i = blockIdx.x * blockDim.x + threadIdx.x;
    if (i == 0) {
        g_counter = 0;
#pragma unroll
        for (int t = 0; t < 3; t++) {
            float nx = planes[4*t+0], ny = planes[4*t+1],
                  nz = planes[4*t+2], d  = planes[4*t+3];
            float s = 2.0f / (nx*nx + ny*ny + nz*nz);
            g_params[t*8+0] = nx;
            g_params[t*8+1] = ny;
            g_params[t*8+2] = nz;
            g_params[t*8+3] = s;
            g_params[t*8+4] = s * d;
        }
#pragma unroll
        for (int t = 0; t < 3; t++) {
            float w = axes[4*t+0], x = axes[4*t+1],
                  y = axes[4*t+2], z = axes[4*t+3];
            // q p q* (pure p, q unnormalized) = [(w^2-|v|^2)I + 2 v v^T + 2 w [v]x] p
            float* m = &g_params[24 + t*12];
            m[0] = w*w + x*x - y*y - z*z;
            m[1] = 2.0f * (x*y - w*z);
            m[2] = 2.0f * (x*z + w*y);
            m[3] = 2.0f * (x*y + w*z);
            m[4] = w*w - x*x + y*y - z*z;
            m[5] = 2.0f * (y*z - w*x);
            m[6] = 2.0f * (x*z - w*y);
            m[7] = 2.0f * (y*z + w*x);
            m[8] = w*w - x*x - y*y + z*z;
        }
    }
    if (i < R3) {
        float4 v;
        v.x = cp[3*i + 0];
        v.y = cp[3*i + 1];
        v.z = cp[3*i + 2];
        v.w = 0.0f;
        g_table[i] = v;
    }
    if (i < NWORDS) {
        unsigned w = 0u;
#pragma unroll 8
        for (int j = 0; j < 32; j++)
            if (vox[i*32 + j] != 0) w |= (1u << j);
        g_bits[i] = w;
    }
}

// ---- voxel index from transformed coords ------------------------------------
__device__ __forceinline__ int vidx(float x, float y, float z) {
    int ix = min(max(__float2int_rd(x * 64.0f), 0), 63);
    int iy = min(max(__float2int_rd(y * 64.0f), 0), 63);
    int iz = min(max(__float2int_rd(z * 64.0f), 0), 63);
    return (ix << 12) | (iy << 6) | iz;
}

// all 6 transforms for one point; batched: transforms -> indices -> mask ->
// gathers, so the 6 conditional LDGs can be issued back-to-back (MLP).
__device__ __forceinline__ float point_all(float x, float y, float z,
                                           const float pn[3][5],
                                           const float m[3][9],
                                           const unsigned* __restrict__ s_bits) {
    float tx[6], ty[6], tz[6];
#pragma unroll
    for (int t = 0; t < 3; t++) {
        float dot  = fmaf(x, pn[t][0], fmaf(y, pn[t][1], z * pn[t][2]));
        float coef = fmaf(dot, pn[t][3], pn[t][4]);
        tx[t] = fmaf(-coef, pn[t][0], x);
        ty[t] = fmaf(-coef, pn[t][1], y);
        tz[t] = fmaf(-coef, pn[t][2], z);
    }
#pragma unroll
    for (int t = 0; t < 3; t++) {
        tx[3+t] = fmaf(x, m[t][0], fmaf(y, m[t][1], z * m[t][2]));
        ty[3+t] = fmaf(x, m[t][3], fmaf(y, m[t][4], z * m[t][5]));
        tz[3+t] = fmaf(x, m[t][6], fmaf(y, m[t][7], z * m[t][8]));
    }
    int  idx[6];
    bool live[6];
#pragma unroll
    for (int t = 0; t < 6; t++) {
        idx[t]  = vidx(tx[t], ty[t], tz[t]);
        live[t] = (s_bits[idx[t] >> 5] >> (idx[t] & 31)) & 1u;
    }
    float acc = 0.0f;
#pragma unroll
    for (int t = 0; t < 6; t++) {
        if (live[t]) {
            float4 c = __ldg(&g_table[idx[t]]);
            float dx = tx[t] - c.x, dy = ty[t] - c.y, dz = tz[t] - c.z;
            acc += sqrtf(fmaf(dx, dx, fmaf(dy, dy, dz * dz)));
        }
    }
    return acc;
}

// ---- main fused kernel (includes last-block final reduction) -----------------
__global__ void __launch_bounds__(NT, 3)
symmetry_main_k(const float* __restrict__ sp, int npts, float* __restrict__ out) {
    __shared__ unsigned s_bits[NWORDS];   // 32 KB
    __shared__ float    s_red[NT / 32];
    __shared__ bool     s_last;

    for (int i = threadIdx.x; i < NWORDS; i += NT)
        s_bits[i] = g_bits[i];
    __syncthreads();

    // loop-invariant params in registers (uniform across block)
    float pn[3][5];
    float m[3][9];
#pragma unroll
    for (int t = 0; t < 3; t++) {
#pragma unroll
        for (int j = 0; j < 5; j++) pn[t][j] = g_params[t*8 + j];
#pragma unroll
        for (int j = 0; j < 9; j++) m[t][j]  = g_params[24 + t*12 + j];
    }

    const float4* sp4 = (const float4*)sp;
    int ngroups = npts >> 2;     // 4 points = 3 float4
    int stride  = gridDim.x * NT;
    float acc = 0.0f;

    for (int g = blockIdx.x * NT + threadIdx.x; g < ngroups; g += stride) {
        float4 A = __ldg(&sp4[3*g + 0]);
        float4 B = __ldg(&sp4[3*g + 1]);
        float4 C = __ldg(&sp4[3*g + 2]);
        float X[4] = {A.x, A.w, B.z, C.y};
        float Y[4] = {A.y, B.x, B.w, C.z};
        float Z[4] = {A.z, B.y, C.x, C.w};
#pragma unroll
        for (int k = 0; k < 4; k++)
            acc += point_all(X[k], Y[k], Z[k], pn, m, s_bits);
    }

    // tail (npts not divisible by 4) — handled by block 0 only
    int tail = npts & 3;
    if (tail && blockIdx.x == 0 && threadIdx.x < tail) {
        int i = npts - tail + threadIdx.x;
        acc += point_all(sp[3*i], sp[3*i+1], sp[3*i+2], pn, m, s_bits);
    }

    // deterministic block reduction
#pragma unroll
    for (int o = 16; o; o >>= 1)
        acc += __shfl_xor_sync(0xFFFFFFFFu, acc, o);
    int lane = threadIdx.x & 31;
    int wid  = threadIdx.x >> 5;
    if (lane == 0) s_red[wid] = acc;
    __syncthreads();
    if (threadIdx.x == 0) {
        float v = 0.0f;
#pragma unroll
        for (int w = 0; w < NT / 32; w++) v += s_red[w];
        g_partials[blockIdx.x] = v;
        __threadfence();
        unsigned old = atomicAdd(&g_counter, 1);
        s_last = (old == (unsigned)(gridDim.x - 1));
    }
    __syncthreads();

    // last-arriving block performs the final deterministic reduction
    if (s_last) {
        __threadfence();
        float v = 0.0f;
        for (int i = threadIdx.x; i < NB; i += NT)
            v += g_partials[i];
#pragma unroll
        for (int o = 16; o; o >>= 1)
            v += __shfl_xor_sync(0xFFFFFFFFu, v, o);
        if (lane == 0) s_red[wid] = v;
        __syncthreads();
        if (threadIdx.x == 0) {
            float u = 0.0f;
#pragma unroll
            for (int w = 0; w < NT / 32; w++) u += s_red[w];
            out[0] = u / (float)npts;
        }
    }
}

// ---- launch ------------------------------------------------------------------
extern "C" void kernel_launch(void* const* d_in, const int* in_sizes, int n_in,
                              void* d_out, int out_size) {
    const float* sp     = (const float*)d_in[0];   // sample_points (N,3)
    const float* cp     = (const float*)d_in[1];   // closest_points (R^3,3)
    const int*   vox    = (const int*)  d_in[2];   // voxels (R^3,)
    const float* planes = (const float*)d_in[3];   // (3,4)
    const float* axes   = (const float*)d_in[4];   // (3,4)
    int npts = in_sizes[0] / 3;

    prep_k<<<(R3 + 255) / 256, 256>>>(cp, vox, planes, axes);
    symmetry_main_k<<<NB, NT>>>(sp, npts, (float*)d_out);
}

// round 3
// speedup vs baseline: 1.5282x; 1.1281x over previous
#include <cuda_runtime.h>

#define RES      64
#define R3       (RES * RES * RES)      // 262144
#define NWORDS   (R3 / 32)              // 8192  (32 KB bitmask)
#define NB       592                    // 148 SMs * 4 blocks
#define NHALF    (NB / 2)               // 296 per transform family
#define NT       256

// ---- scratch (no allocations allowed) --------------------------------------
__device__ float4   g_table[R3];        // closest point per voxel (w unused)
__device__ unsigned g_bits[NWORDS];     // voxel occupancy bitmask
__device__ float    g_params[64];       // [t*8+{0..4}]: refl ; [24+t*12+{0..8}]: rot matrix
__device__ float    g_partials[NB];
__device__ int      g_counter;

// ---- prep: params + float4 table + bitmask + counter reset (one kernel) -----
__global__ void prep_k(const float* __restrict__ cp,
                       const int*   __restrict__ vox,
                       const float* __restrict__ planes,
                       const float* __restrict__ axes) {
    int i = blockIdx.x * blockDim.x + threadIdx.x;
    if (i == 0) {
        g_counter = 0;
#pragma unroll
        for (int t = 0; t < 3; t++) {
            float nx = planes[4*t+0], ny = planes[4*t+1],
                  nz = planes[4*t+2], d  = planes[4*t+3];
            float s = 2.0f / (nx*nx + ny*ny + nz*nz);
            g_params[t*8+0] = nx;
            g_params[t*8+1] = ny;
            g_params[t*8+2] = nz;
            g_params[t*8+3] = s;
            g_params[t*8+4] = s * d;
        }
#pragma unroll
        for (int t = 0; t < 3; t++) {
            float w = axes[4*t+0], x = axes[4*t+1],
                  y = axes[4*t+2], z = axes[4*t+3];
            // q p q* (pure p, q unnormalized) = [(w^2-|v|^2)I + 2 v v^T + 2 w [v]x] p
            float* m = &g_params[24 + t*12];
            m[0] = w*w + x*x - y*y - z*z;
            m[1] = 2.0f * (x*y - w*z);
            m[2] = 2.0f * (x*z + w*y);
            m[3] = 2.0f * (x*y + w*z);
            m[4] = w*w - x*x + y*y - z*z;
            m[5] = 2.0f * (y*z - w*x);
            m[6] = 2.0f * (x*z - w*y);
            m[7] = 2.0f * (y*z + w*x);
            m[8] = w*w - x*x - y*y + z*z;
        }
    }
    if (i < R3) {
        float4 v;
        v.x = cp[3*i + 0];
        v.y = cp[3*i + 1];
        v.z = cp[3*i + 2];
        v.w = 0.0f;
        g_table[i] = v;
    }
    if (i < NWORDS) {
        unsigned w = 0u;
#pragma unroll 8
        for (int j = 0; j < 32; j++)
            if (vox[i*32 + j] != 0) w |= (1u << j);
        g_bits[i] = w;
    }
}

// ---- voxel index from transformed coords ------------------------------------
__device__ __forceinline__ int vidx(float x, float y, float z) {
    int ix = min(max(__float2int_rd(x * 64.0f), 0), 63);
    int iy = min(max(__float2int_rd(y * 64.0f), 0), 63);
    int iz = min(max(__float2int_rd(z * 64.0f), 0), 63);
    return (ix << 12) | (iy << 6) | iz;
}

// 3 taps for one point: transforms -> indices -> mask -> batched gathers
__device__ __forceinline__ float taps3(const float tx[3], const float ty[3],
                                       const float tz[3],
                                       const unsigned* __restrict__ s_bits) {
    int  idx[3];
    bool live[3];
#pragma unroll
    for (int t = 0; t < 3; t++) {
        idx[t]  = vidx(tx[t], ty[t], tz[t]);
        live[t] = (s_bits[idx[t] >> 5] >> (idx[t] & 31)) & 1u;
    }
    float acc = 0.0f;
#pragma unroll
    for (int t = 0; t < 3; t++) {
        if (live[t]) {
            float4 c = __ldg(&g_table[idx[t]]);
            float dx = tx[t] - c.x, dy = ty[t] - c.y, dz = tz[t] - c.z;
            acc += sqrtf(fmaf(dx, dx, fmaf(dy, dy, dz * dz)));
        }
    }
    return acc;
}

__device__ __forceinline__ float point_refl(float x, float y, float z,
                                            const float pn[3][5],
                                            const unsigned* __restrict__ s_bits) {
    float tx[3], ty[3], tz[3];
#pragma unroll
    for (int t = 0; t < 3; t++) {
        float dot  = fmaf(x, pn[t][0], fmaf(y, pn[t][1], z * pn[t][2]));
        float coef = fmaf(dot, pn[t][3], pn[t][4]);
        tx[t] = fmaf(-coef, pn[t][0], x);
        ty[t] = fmaf(-coef, pn[t][1], y);
        tz[t] = fmaf(-coef, pn[t][2], z);
    }
    return taps3(tx, ty, tz, s_bits);
}

__device__ __forceinline__ float point_rot(float x, float y, float z,
                                           const float m[3][9],
                                           const unsigned* __restrict__ s_bits) {
    float tx[3], ty[3], tz[3];
#pragma unroll
    for (int t = 0; t < 3; t++) {
        tx[t] = fmaf(x, m[t][0], fmaf(y, m[t][1], z * m[t][2]));
        ty[t] = fmaf(x, m[t][3], fmaf(y, m[t][4], z * m[t][5]));
        tz[t] = fmaf(x, m[t][6], fmaf(y, m[t][7], z * m[t][8]));
    }
    return taps3(tx, ty, tz, s_bits);
}

// ---- main kernel: blocks [0,NHALF) do reflections, [NHALF,NB) rotations ------
__global__ void __launch_bounds__(NT, 4)
symmetry_main_k(const float* __restrict__ sp, int npts, float* __restrict__ out) {
    __shared__ unsigned s_bits[NWORDS];   // 32 KB
    __shared__ float    s_red[NT / 32];
    __shared__ bool     s_last;

    for (int i = threadIdx.x; i < NWORDS; i += NT)
        s_bits[i] = g_bits[i];
    __syncthreads();

    const bool is_rot = (blockIdx.x >= NHALF);
    const int  bid    = is_rot ? (blockIdx.x - NHALF) : blockIdx.x;

    const float4* sp4 = (const float4*)sp;
    const int ngroups = npts >> 2;     // 4 points = 3 float4
    const int stride  = NHALF * NT;
    const int tail    = npts & 3;
    float acc = 0.0f;

    if (!is_rot) {
        float pn[3][5];
#pragma unroll
        for (int t = 0; t < 3; t++)
#pragma unroll
            for (int j = 0; j < 5; j++) pn[t][j] = g_params[t*8 + j];

        for (int g = bid * NT + threadIdx.x; g < ngroups; g += stride) {
            float4 A = __ldg(&sp4[3*g + 0]);
            float4 B = __ldg(&sp4[3*g + 1]);
            float4 C = __ldg(&sp4[3*g + 2]);
            float X[4] = {A.x, A.w, B.z, C.y};
            float Y[4] = {A.y, B.x, B.w, C.z};
            float Z[4] = {A.z, B.y, C.x, C.w};
#pragma unroll
            for (int k = 0; k < 4; k++)
                acc += point_refl(X[k], Y[k], Z[k], pn, s_bits);
        }
        if (tail && bid == 0 && threadIdx.x < tail) {
            int i = npts - tail + threadIdx.x;
            acc += point_refl(sp[3*i], sp[3*i+1], sp[3*i+2], pn, s_bits);
        }
    } else {
        float m[3][9];
#pragma unroll
        for (int t = 0; t < 3; t++)
#pragma unroll
            for (int j = 0; j < 9; j++) m[t][j] = g_params[24 + t*12 + j];

        for (int g = bid * NT + threadIdx.x; g < ngroups; g += stride) {
            float4 A = __ldg(&sp4[3*g + 0]);
            float4 B = __ldg(&sp4[3*g + 1]);
            float4 C = __ldg(&sp4[3*g + 2]);
            float X[4] = {A.x, A.w, B.z, C.y};
            float Y[4] = {A.y, B.x, B.w, C.z};
            float Z[4] = {A.z, B.y, C.x, C.w};
#pragma unroll
            for (int k = 0; k < 4; k++)
                acc += point_rot(X[k], Y[k], Z[k], m, s_bits);
        }
        if (tail && bid == 0 && threadIdx.x < tail) {
            int i = npts - tail + threadIdx.x;
            acc += point_rot(sp[3*i], sp[3*i+1], sp[3*i+2], m, s_bits);
        }
    }

    // deterministic block reduction
#pragma unroll
    for (int o = 16; o; o >>= 1)
        acc += __shfl_xor_sync(0xFFFFFFFFu, acc, o);
    int lane = threadIdx.x & 31;
    int wid  = threadIdx.x >> 5;
    if (lane == 0) s_red[wid] = acc;
    __syncthreads();
    if (threadIdx.x == 0) {
        float v = 0.0f;
#pragma unroll
        for (int w = 0; w < NT / 32; w++) v += s_red[w];
        g_partials[blockIdx.x] = v;
        __threadfence();
        unsigned old = atomicAdd(&g_counter, 1);
        s_last = (old == (unsigned)(gridDim.x - 1));
    }
    __syncthreads();

    // last-arriving block performs the final deterministic reduction
    if (s_last) {
        __threadfence();
        float v = 0.0f;
        for (int i = threadIdx.x; i < NB; i += NT)
            v += g_partials[i];
#pragma unroll
        for (int o = 16; o; o >>= 1)
            v += __shfl_xor_sync(0xFFFFFFFFu, v, o);
        if (lane == 0) s_red[wid] = v;
        __syncthreads();
        if (threadIdx.x == 0) {
            float u = 0.0f;
#pragma unroll
            for (int w = 0; w < NT / 32; w++) u += s_red[w];
            out[0] = u / (float)npts;
        }
    }
}

// ---- launch ------------------------------------------------------------------
extern "C" void kernel_launch(void* const* d_in, const int* in_sizes, int n_in,
                              void* d_out, int out_size) {
    const float* sp     = (const float*)d_in[0];   // sample_points (N,3)
    const float* cp     = (const float*)d_in[1];   // closest_points (R^3,3)
    const int*   vox    = (const int*)  d_in[2];   // voxels (R^3,)
    const float* planes = (const float*)d_in[3];   // (3,4)
    const float* axes   = (const float*)d_in[4];   // (3,4)
    int npts = in_sizes[0] / 3;

    prep_k<<<(R3 + 255) / 256, 256>>>(cp, vox, planes, axes);
    symmetry_main_k<<<NB, NT>>>(sp, npts, (float*)d_out);
}